// round 1
// baseline (speedup 1.0000x reference)
#include <cuda_runtime.h>
#include <cuda_bf16.h>

// Spatially-varying 19x19 blur.
// out[b,c,i,j] = (1/361) * sum_{u,v} x_reflectpad[b,c,i+u-9,j+v-9] * kernel[b,u*19+v,i,j]
//
// B=2, C=3, H=W=256, L=19, K2=361.
// Dominant traffic: kernel tensor (189 MB) read exactly once -> HBM bound.

#define LK    19
#define PADR  9
#define HGT   256
#define WID   256
#define HW    (HGT * WID)
#define K2    (LK * LK)

#define TJ    32      // tile width (pixels)
#define TI    8       // tile height (pixels)
#define JT    8       // j-threads per row (each handles 4 px)
#define NTHR  64      // JT * TI
#define PCOLS (TJ + LK - 1)   // 50
#define PROWS (TI + LK - 1)   // 26
#define PITCH 53              // odd pitch -> conflict-free scalar LDS

__global__ __launch_bounds__(NTHR)
void svblur_kernel(const float* __restrict__ x,
                   const float* __restrict__ kern,
                   float* __restrict__ out)
{
    __shared__ float sm[3][PROWS][PITCH];   // 3*26*53*4 = 16536 B

    const int tid = threadIdx.x;
    const int jt  = blockIdx.x;   // 0..7
    const int it  = blockIdx.y;   // 0..31
    const int b   = blockIdx.z;   // 0..1

    const int j0 = jt * TJ;
    const int i0 = it * TI;

    // ---- stage input patch (reflect padding) into smem ----
    const float* xb = x + (size_t)b * 3 * HW;
    #pragma unroll
    for (int c = 0; c < 3; c++) {
        for (int e = tid; e < PROWS * PCOLS; e += NTHR) {
            int pr = e / PCOLS;
            int pc = e - pr * PCOLS;
            int gi = i0 - PADR + pr;
            int gj = j0 - PADR + pc;
            gi = (gi < 0) ? -gi : ((gi >= HGT) ? 2 * (HGT - 1) - gi : gi);
            gj = (gj < 0) ? -gj : ((gj >= WID) ? 2 * (WID - 1) - gj : gj);
            sm[c][pr][pc] = xb[(size_t)c * HW + gi * WID + gj];
        }
    }
    __syncthreads();

    const int jth = tid & (JT - 1);   // 0..7
    const int ir  = tid >> 3;         // 0..7
    const int i   = i0 + ir;
    const int jj  = jth * 4;          // local j of first of 4 pixels
    const int j   = j0 + jj;

    // kernel plane pointer for this pixel group; step HW floats (=HW/4 float4) per k
    const float4* kp = (const float4*)(kern + (size_t)b * K2 * HW + (size_t)i * WID + j);

    float acc0[4] = {0.f, 0.f, 0.f, 0.f};
    float acc1[4] = {0.f, 0.f, 0.f, 0.f};
    float acc2[4] = {0.f, 0.f, 0.f, 0.f};

    for (int u = 0; u < LK; u++) {
        // sliding input windows for this row, all 3 channels
        float w0[LK + 3], w1[LK + 3], w2[LK + 3];
        #pragma unroll
        for (int t = 0; t < LK + 3; t++) {
            w0[t] = sm[0][ir + u][jj + t];
            w1[t] = sm[1][ir + u][jj + t];
            w2[t] = sm[2][ir + u][jj + t];
        }
        const float4* kpu = kp + (size_t)u * LK * (HW / 4);
        #pragma unroll
        for (int v = 0; v < LK; v++) {
            float4 kv = __ldg(&kpu[(size_t)v * (HW / 4)]);
            acc0[0] += w0[v + 0] * kv.x;
            acc0[1] += w0[v + 1] * kv.y;
            acc0[2] += w0[v + 2] * kv.z;
            acc0[3] += w0[v + 3] * kv.w;
            acc1[0] += w1[v + 0] * kv.x;
            acc1[1] += w1[v + 1] * kv.y;
            acc1[2] += w1[v + 2] * kv.z;
            acc1[3] += w1[v + 3] * kv.w;
            acc2[0] += w2[v + 0] * kv.x;
            acc2[1] += w2[v + 1] * kv.y;
            acc2[2] += w2[v + 2] * kv.z;
            acc2[3] += w2[v + 3] * kv.w;
        }
    }

    const float inv = 1.0f / (float)K2;
    float* ob = out + (size_t)b * 3 * HW + (size_t)i * WID + j;
    float4 o0 = make_float4(acc0[0] * inv, acc0[1] * inv, acc0[2] * inv, acc0[3] * inv);
    float4 o1 = make_float4(acc1[0] * inv, acc1[1] * inv, acc1[2] * inv, acc1[3] * inv);
    float4 o2 = make_float4(acc2[0] * inv, acc2[1] * inv, acc2[2] * inv, acc2[3] * inv);
    *(float4*)(ob + 0 * HW) = o0;
    *(float4*)(ob + 1 * HW) = o1;
    *(float4*)(ob + 2 * HW) = o2;
}

extern "C" void kernel_launch(void* const* d_in, const int* in_sizes, int n_in,
                              void* d_out, int out_size)
{
    const float* x    = (const float*)d_in[0];
    const float* kern = (const float*)d_in[1];
    // defensive: identify tensors by size (input = 393216, kernel = 47316992)
    if (n_in >= 2 && in_sizes[0] > in_sizes[1]) {
        const float* t = x; x = kern; kern = t;
    }

    dim3 grid(WID / TJ, HGT / TI, 2);   // (8, 32, 2) = 512 blocks
    svblur_kernel<<<grid, NTHR>>>(x, kern, (float*)d_out);
}

// round 2
// speedup vs baseline: 1.3384x; 1.3384x over previous
#include <cuda_runtime.h>
#include <cuda_bf16.h>

// Spatially-varying 19x19 blur.
// out[b,c,i,j] = (1/361) * sum_{u,v} x_reflectpad[b,c,i+u-9,j+v-9] * kernel[b,u*19+v,i,j]
//
// B=2, C=3, H=W=256, L=19, K2=361.
// Kernel tensor (189 MB) dominates traffic; read exactly once -> HBM bound.
// R2: 1 pixel x 3 channels per thread -> 4096 warps (~43% occ) for latency hiding.

#define LK    19
#define PADR  9
#define HGT   256
#define WID   256
#define HW    (HGT * WID)
#define K2    (LK * LK)

#define TJ    32      // tile width  (pixels) == warp width
#define TI    8       // tile height (pixels)
#define NTHR  (TJ * TI)          // 256 threads, 8 warps
#define PCOLS (TJ + LK - 1)      // 50
#define PROWS (TI + LK - 1)      // 26
#define PITCH 50                 // lanes read consecutive floats -> conflict-free

__global__ __launch_bounds__(NTHR)
void svblur_kernel(const float* __restrict__ x,
                   const float* __restrict__ kern,
                   float* __restrict__ out)
{
    __shared__ float sm[3][PROWS][PITCH];   // 3*26*50*4 = 15600 B

    const int tid = threadIdx.x;
    const int jt  = blockIdx.x;   // 0..7
    const int it  = blockIdx.y;   // 0..31
    const int b   = blockIdx.z;   // 0..1

    const int j0 = jt * TJ;
    const int i0 = it * TI;

    // ---- stage input patch (reflect padding) into smem, all 3 channels ----
    const float* xb = x + (size_t)b * 3 * HW;
    for (int e = tid; e < PROWS * PCOLS; e += NTHR) {
        int pr = e / PCOLS;
        int pc = e - pr * PCOLS;
        int gi = i0 - PADR + pr;
        int gj = j0 - PADR + pc;
        gi = (gi < 0) ? -gi : ((gi >= HGT) ? 2 * (HGT - 1) - gi : gi);
        gj = (gj < 0) ? -gj : ((gj >= WID) ? 2 * (WID - 1) - gj : gj);
        const float* src = xb + gi * WID + gj;
        sm[0][pr][pc] = src[0 * HW];
        sm[1][pr][pc] = src[1 * HW];
        sm[2][pr][pc] = src[2 * HW];
    }
    __syncthreads();

    const int jl = tid & (TJ - 1);    // lane within row: 0..31
    const int ir = tid >> 5;          // row within tile: 0..7
    const int i  = i0 + ir;
    const int j  = j0 + jl;

    // kernel plane pointer for this pixel; step HW floats per tap index
    const float* kp = kern + (size_t)b * K2 * HW + (size_t)i * WID + j;

    float a0 = 0.f, a1 = 0.f, a2 = 0.f;

    #pragma unroll 1
    for (int u = 0; u < LK; u++) {
        const float* kr  = kp + (size_t)u * LK * HW;
        const float* s0  = &sm[0][ir + u][jl];
        const float* s1  = &sm[1][ir + u][jl];
        const float* s2  = &sm[2][ir + u][jl];
        #pragma unroll
        for (int v = 0; v < LK; v++) {
            float kv = __ldg(kr + (size_t)v * HW);
            a0 += s0[v] * kv;
            a1 += s1[v] * kv;
            a2 += s2[v] * kv;
        }
    }

    const float inv = 1.0f / (float)K2;
    float* ob = out + (size_t)b * 3 * HW + (size_t)i * WID + j;
    ob[0 * HW] = a0 * inv;
    ob[1 * HW] = a1 * inv;
    ob[2 * HW] = a2 * inv;
}

extern "C" void kernel_launch(void* const* d_in, const int* in_sizes, int n_in,
                              void* d_out, int out_size)
{
    const float* x    = (const float*)d_in[0];
    const float* kern = (const float*)d_in[1];
    // defensive: identify tensors by size (input = 393216, kernel = 47316992)
    if (n_in >= 2 && in_sizes[0] > in_sizes[1]) {
        const float* t = x; x = kern; kern = t;
    }

    dim3 grid(WID / TJ, HGT / TI, 2);   // (8, 32, 2) = 512 blocks, 8 warps each
    svblur_kernel<<<grid, NTHR>>>(x, kern, (float*)d_out);
}